// round 9
// baseline (speedup 1.0000x reference)
#include <cuda_runtime.h>
#include <cuda_fp16.h>
#include <math.h>

#define HDIM 32
#define NDIM 1024
#define BATCH 8
#define NT 256              // LUT resolution; fp16 quant dominates err (~1.8e-4, budget 1e-3)
#define NTILES (BATCH * 32 * 32)   // 8192 ordered (b, ti, tj) tiles
#define UNITS_PER_BLOCK 8
#define GRID (NTILES / UNITS_PER_BLOCK)   // 1024 blocks x 8 units

// LUT entry i = half2(0.5*f(i/NT), 0.5*f((i+1)/NT)); 0.5 symmetrization folded in.
__device__ __half2 g_lut_h2[NT];

// ---------------------------------------------------------------------------
// Kernel 1: build LUT. One WARP per sample point.
// ---------------------------------------------------------------------------
__global__ void build_lut_kernel(const float* __restrict__ w1,
                                 const float* __restrict__ b1,
                                 const float* __restrict__ w2,
                                 const float* __restrict__ b2,
                                 const float* __restrict__ w3,
                                 const float* __restrict__ b3) {
    const int gwarp = (blockIdx.x * blockDim.x + threadIdx.x) >> 5;
    const int lane  = threadIdx.x & 31;
    if (gwarp > NT) return;

    const float x = (float)gwarp * (1.0f / (float)NT);
    float h1 = fmaxf(fmaf(x, w1[lane], b1[lane]), 0.0f);
    float s = b2[lane];
#pragma unroll
    for (int h = 0; h < HDIM; h++) {
        float h1h = __shfl_sync(0xffffffffu, h1, h);
        s = fmaf(h1h, w2[h * HDIM + lane], s);
    }
    float part = fmaxf(s, 0.0f) * w3[lane];
#pragma unroll
    for (int off = 16; off > 0; off >>= 1)
        part += __shfl_xor_sync(0xffffffffu, part, off);

    if (lane == 0) {
        float f = 0.5f / (1.0f + expf(-(part + b3[0])));   // 0.5 folded in
        __half fh = __float2half_rn(f);
        __half* hp = (__half*)g_lut_h2;
        if (gwarp < NT) hp[2 * gwarp]     = fh;   // entry gwarp .x
        if (gwarp > 0)  hp[2 * gwarp - 1] = fh;   // entry gwarp-1 .y
    }
}

// ---------------------------------------------------------------------------
// Conflict-free LUT lookup: entry i for lane l lives at word i*32+l -> bank=l
// always, zero replays. No clamp needed (x in [0,1) by construction).
// ---------------------------------------------------------------------------
__device__ __forceinline__ float lutf(const __half2* __restrict__ slut,
                                      int lane, float x) {
    float u = x * (float)NT;
    int i = (int)u;
    float2 v = __half22float2(slut[(i << 5) + lane]);
    return fmaf(u - (float)i, v.y - v.x, v.x);
}

// ---------------------------------------------------------------------------
// Kernel 2: barrier-free register-tile design, one tile per 64-thread unit,
// 8 units per 512-thread block (staging amortized 8x, 3 blocks/SM resident).
// Unit handles ordered tile (b, ti, tj); thread owns a 4x4 output block:
//   out(r,c) = (f(A[r][c]) + f(A[c][r])) * mi[r] * mj[c]   (0.5 folded in LUT)
// 8 independent LDG.128 per thread, 32 conflict-free LDS lookups, 4 coalesced
// STG.128. Single barrier (LUT staging).
// ---------------------------------------------------------------------------
__global__ void __launch_bounds__(512)
corrector_kernel(const float* __restrict__ sim,
                 const int* __restrict__ masks,
                 float* __restrict__ out) {
    __shared__ __half2 slut[NT * 32];   // 32 KB bank-replicated LUT

    const int tid  = threadIdx.x;
    const int lane = tid & 31;

    // stage LUT: word w = entry(w>>5) for lane (w&31); broadcast LDG, CF STS
#pragma unroll
    for (int k = 0; k < 16; k++) {
        int w = tid + 512 * k;
        slut[w] = g_lut_h2[w >> 5];
    }
    __syncthreads();   // the only barrier

    const int t64 = tid & 63;
    const int r0  = (t64 >> 3) << 2;   // 0,4,...,28
    const int c0  = (t64 & 7) << 2;    // 0,4,...,28

    const int u  = blockIdx.x * UNITS_PER_BLOCK + (tid >> 6);  // tile id
    const int b  = u >> 10;
    const int ti = (u >> 5) & 31;
    const int tj = u & 31;

    const float* __restrict__ simb = sim + (size_t)b * (NDIM * NDIM);

    // 8 independent loads (fwd rows coalesced; transposed rows 64B-chunked)
    float4 aR[4], bR[4];
#pragma unroll
    for (int a = 0; a < 4; a++)
        aR[a] = *(const float4*)(simb + (size_t)(ti * 32 + r0 + a) * NDIM + tj * 32 + c0);
#pragma unroll
    for (int k = 0; k < 4; k++)
        bR[k] = *(const float4*)(simb + (size_t)(tj * 32 + c0 + k) * NDIM + ti * 32 + r0);

    const int4 mi4 = *(const int4*)(masks + b * NDIM + ti * 32 + r0);
    const int4 mj4 = *(const int4*)(masks + b * NDIM + tj * 32 + c0);
    float mif[4] = {(float)mi4.x, (float)mi4.y, (float)mi4.z, (float)mi4.w};
    float mjf[4] = {(float)mj4.x, (float)mj4.y, (float)mj4.z, (float)mj4.w};

    // 32 conflict-free lookups
    float ga[4][4], gb[4][4];
#pragma unroll
    for (int a = 0; a < 4; a++) {
        ga[a][0] = lutf(slut, lane, aR[a].x);
        ga[a][1] = lutf(slut, lane, aR[a].y);
        ga[a][2] = lutf(slut, lane, aR[a].z);
        ga[a][3] = lutf(slut, lane, aR[a].w);
    }
#pragma unroll
    for (int k = 0; k < 4; k++) {
        gb[k][0] = lutf(slut, lane, bR[k].x);
        gb[k][1] = lutf(slut, lane, bR[k].y);
        gb[k][2] = lutf(slut, lane, bR[k].z);
        gb[k][3] = lutf(slut, lane, bR[k].w);
    }

    const bool dg = (ti == tj);
    float* __restrict__ outb = out + (size_t)b * (NDIM * NDIM);
#pragma unroll
    for (int a = 0; a < 4; a++) {
        float4 v;
        v.x = (ga[a][0] + gb[0][a]) * (mif[a] * mjf[0]);
        v.y = (ga[a][1] + gb[1][a]) * (mif[a] * mjf[1]);
        v.z = (ga[a][2] + gb[2][a]) * (mif[a] * mjf[2]);
        v.w = (ga[a][3] + gb[3][a]) * (mif[a] * mjf[3]);
        if (dg) {   // zero global diagonal (only inside diagonal tiles)
            if (r0 + a == c0 + 0) v.x = 0.0f;
            if (r0 + a == c0 + 1) v.y = 0.0f;
            if (r0 + a == c0 + 2) v.z = 0.0f;
            if (r0 + a == c0 + 3) v.w = 0.0f;
        }
        *(float4*)(outb + (size_t)(ti * 32 + r0 + a) * NDIM + tj * 32 + c0) = v;
    }
}

// ---------------------------------------------------------------------------
// Harness entry
// ---------------------------------------------------------------------------
extern "C" void kernel_launch(void* const* d_in, const int* in_sizes, int n_in,
                              void* d_out, int out_size) {
    const float* sim   = (const float*)d_in[0];
    const int*   masks = (const int*)d_in[1];
    const float* w1    = (const float*)d_in[2];
    const float* b1    = (const float*)d_in[3];
    const float* w2    = (const float*)d_in[4];
    const float* b2    = (const float*)d_in[5];
    const float* w3    = (const float*)d_in[6];
    const float* b3    = (const float*)d_in[7];
    float* out = (float*)d_out;

    build_lut_kernel<<<65, 128>>>(w1, b1, w2, b2, w3, b3);
    corrector_kernel<<<GRID, 512>>>(sim, masks, out);
}

// round 10
// speedup vs baseline: 1.1562x; 1.1562x over previous
#include <cuda_runtime.h>
#include <cuda_fp16.h>
#include <math.h>

#define HDIM 32
#define NDIM 1024
#define BATCH 8
#define NT 256              // LUT resolution; fp16 quant dominates err (~1.8e-4, budget 1e-3)
#define TILE 32
#define TPAIRS 528
#define NPAIRS (BATCH * TPAIRS)   // 4224
#define PPH 4                     // pairs per half-block
#define GRID (NPAIRS / (2 * PPH)) // 528 blocks

// LUT entry i = half2(0.5*f(i/NT), 0.5*f((i+1)/NT)); 0.5 symmetrization folded in.
__device__ __half2 g_lut_h2[NT];
__device__ int g_unrank[TPAIRS];   // t -> ti | (tj<<8)

// ---------------------------------------------------------------------------
// Kernel 1: build LUT (one warp per sample) + unrank table.
// ---------------------------------------------------------------------------
__global__ void build_lut_kernel(const float* __restrict__ w1,
                                 const float* __restrict__ b1,
                                 const float* __restrict__ w2,
                                 const float* __restrict__ b2,
                                 const float* __restrict__ w3,
                                 const float* __restrict__ b3) {
    const int gtid  = blockIdx.x * blockDim.x + threadIdx.x;
    const int gwarp = gtid >> 5;
    const int lane  = threadIdx.x & 31;

    if (gtid < TPAIRS) {
        int t = gtid, ti = 0;
        while (t >= TILE - ti) { t -= TILE - ti; ti++; }
        g_unrank[gtid] = ti | ((ti + t) << 8);
    }
    if (gwarp > NT) return;

    const float x = (float)gwarp * (1.0f / (float)NT);
    float h1 = fmaxf(fmaf(x, w1[lane], b1[lane]), 0.0f);
    float s = b2[lane];
#pragma unroll
    for (int h = 0; h < HDIM; h++) {
        float h1h = __shfl_sync(0xffffffffu, h1, h);
        s = fmaf(h1h, w2[h * HDIM + lane], s);
    }
    float part = fmaxf(s, 0.0f) * w3[lane];
#pragma unroll
    for (int off = 16; off > 0; off >>= 1)
        part += __shfl_xor_sync(0xffffffffu, part, off);

    if (lane == 0) {
        float f = 0.5f / (1.0f + expf(-(part + b3[0])));   // 0.5 folded in
        __half fh = __float2half_rn(f);
        __half* hp = (__half*)g_lut_h2;
        if (gwarp < NT) hp[2 * gwarp]     = fh;
        if (gwarp > 0)  hp[2 * gwarp - 1] = fh;
    }
}

// ---------------------------------------------------------------------------
// Conflict-free LUT lookup: entry i for lane l at word i*32+l -> bank=l always.
// ---------------------------------------------------------------------------
__device__ __forceinline__ float lutf(const __half2* __restrict__ slut,
                                      int lane, float x) {
    float u = x * (float)NT;
    int i = (int)u;
    float2 v = __half22float2(slut[(i << 5) + lane]);
    return fmaf(u - (float)i, v.y - v.x, v.x);
}

// ---------------------------------------------------------------------------
// Kernel 2: single-read symmetric pair design + conflict-free LUT.
// 512-thread block = 2 halves; each half processes PPH=4 (b, ti<=tj) pairs.
//   fwd(r,c)    = fA[r][c] + fB[c][r]
//   mirror(r,c) = fB[r][c] + fA[c][r]
// (fA,fB) staged once as XOR-swizzled float2; one transposed LDS.64 per
// element serves both output tiles. LUT (32 KB replicated) staged once per
// block, amortized over 8 pairs.
// ---------------------------------------------------------------------------
__global__ void __launch_bounds__(512)
corrector_kernel(const float* __restrict__ sim,
                 const int* __restrict__ masks,
                 float* __restrict__ out) {
    __shared__ __half2 slut[NT * 32];            // 32 KB replicated LUT
    __shared__ float2  sF[2][TILE * TILE];       // 16 KB (fA,fB) swizzled
    __shared__ __align__(16) float smi[2][TILE];
    __shared__ __align__(16) float smj[2][TILE];

    const int tid  = threadIdx.x;
    const int lane = tid & 31;
    const int half = tid >> 8;
    const int htid = tid & 255;
    const int r    = htid >> 3;
    const int c0   = (htid & 7) * 4;

    // stage replicated LUT: word w = entry(w>>5) for lane (w&31)
#pragma unroll
    for (int k = 0; k < 16; k++) {
        int w = tid + 512 * k;
        slut[w] = g_lut_h2[w >> 5];
    }
    float2* sFh = sF[half];
    const int sbase = r * 32 + (c0 ^ r);
    const int lbase = c0 * 32 + (r ^ c0);
    __syncthreads();

#pragma unroll 1
    for (int it = 0; it < PPH; it++) {
        const int p = (blockIdx.x * 2 + half) * PPH + it;
        const int b = p / TPAIRS;
        const int code = __ldg(&g_unrank[p - b * TPAIRS]);
        const int ti = code & 255;
        const int tj = code >> 8;
        const bool diag = (ti == tj);

        const float* __restrict__ simb = sim + (size_t)b * (NDIM * NDIM);
        float*       __restrict__ outb = out + (size_t)b * (NDIM * NDIM);

        // stage masks (as float 0/1)
        if (htid < TILE)          smi[half][htid]      = (float)masks[b * NDIM + ti * TILE + htid];
        else if (htid < 2 * TILE) smj[half][htid - 32] = (float)masks[b * NDIM + tj * TILE + (htid - 32)];

        // single-read tile loads
        float4 a4 = *(const float4*)(simb + (size_t)(ti * TILE + r) * NDIM + tj * TILE + c0);
        float4 b4 = diag ? a4
                         : *(const float4*)(simb + (size_t)(tj * TILE + r) * NDIM + ti * TILE + c0);

        // 8 conflict-free lookups
        float fA0 = lutf(slut, lane, a4.x), fA1 = lutf(slut, lane, a4.y);
        float fA2 = lutf(slut, lane, a4.z), fA3 = lutf(slut, lane, a4.w);
        float fB0 = lutf(slut, lane, b4.x), fB1 = lutf(slut, lane, b4.y);
        float fB2 = lutf(slut, lane, b4.z), fB3 = lutf(slut, lane, b4.w);

        // XOR-swizzled stage: elem(row,col) -> row*32 + (col^row)
        sFh[sbase ^ 0] = make_float2(fA0, fB0);
        sFh[sbase ^ 1] = make_float2(fA1, fB1);
        sFh[sbase ^ 2] = make_float2(fA2, fB2);
        sFh[sbase ^ 3] = make_float2(fA3, fB3);
        __syncthreads();

        // transposed gather: elem(c0+k, r) at ((lbase)^k) + 32k
        float2 p0 = sFh[(lbase ^ 0)];
        float2 p1 = sFh[(lbase ^ 1) + 32];
        float2 p2 = sFh[(lbase ^ 2) + 64];
        float2 p3 = sFh[(lbase ^ 3) + 96];

        const float mi_r = smi[half][r], mj_r = smj[half][r];
        const float4 mj4 = *(const float4*)&smj[half][c0];
        const float4 mi4 = *(const float4*)&smi[half][c0];

        float4 vf;   // fwd tile (ti,tj) row r
        vf.x = (fA0 + p0.y) * (mi_r * mj4.x);
        vf.y = (fA1 + p1.y) * (mi_r * mj4.y);
        vf.z = (fA2 + p2.y) * (mi_r * mj4.z);
        vf.w = (fA3 + p3.y) * (mi_r * mj4.w);
        if (diag) {
            if (r == c0 + 0) vf.x = 0.0f;
            if (r == c0 + 1) vf.y = 0.0f;
            if (r == c0 + 2) vf.z = 0.0f;
            if (r == c0 + 3) vf.w = 0.0f;
        }
        *(float4*)(outb + (size_t)(ti * TILE + r) * NDIM + tj * TILE + c0) = vf;

        if (!diag) {
            float4 vm;  // mirror tile (tj,ti) row r
            vm.x = (fB0 + p0.x) * (mj_r * mi4.x);
            vm.y = (fB1 + p1.x) * (mj_r * mi4.y);
            vm.z = (fB2 + p2.x) * (mj_r * mi4.z);
            vm.w = (fB3 + p3.x) * (mj_r * mi4.w);
            *(float4*)(outb + (size_t)(tj * TILE + r) * NDIM + ti * TILE + c0) = vm;
        }
        __syncthreads();   // protect sF/masks overwrite next iteration
    }
}

// ---------------------------------------------------------------------------
// Harness entry
// ---------------------------------------------------------------------------
extern "C" void kernel_launch(void* const* d_in, const int* in_sizes, int n_in,
                              void* d_out, int out_size) {
    const float* sim   = (const float*)d_in[0];
    const int*   masks = (const int*)d_in[1];
    const float* w1    = (const float*)d_in[2];
    const float* b1    = (const float*)d_in[3];
    const float* w2    = (const float*)d_in[4];
    const float* b2    = (const float*)d_in[5];
    const float* w3    = (const float*)d_in[6];
    const float* b3    = (const float*)d_in[7];
    float* out = (float*)d_out;

    build_lut_kernel<<<65, 128>>>(w1, b1, w2, b2, w3, b3);
    corrector_kernel<<<GRID, 512>>>(sim, masks, out);
}

// round 11
// speedup vs baseline: 1.3378x; 1.1571x over previous
#include <cuda_runtime.h>
#include <cuda_fp16.h>
#include <math.h>

#define HDIM 32
#define NDIM 1024
#define BATCH 8
#define NT 32               // LUT now register-resident: entry per lane, shfl lookup
#define TILE 32
#define TPAIRS 528          // 32*33/2 upper-triangular tile pairs
#define NPAIRS (BATCH * TPAIRS)   // 4224 = 2112 blocks x 2 halves

// LUT entry i = half2(0.5*f(i/NT), 0.5*f((i+1)/NT)); 0.5 symmetrization folded in.
__device__ __half2 g_lut_h2[NT];
// unrank table: t -> ti | (tj<<8)
__device__ int g_unrank[TPAIRS];

// ---------------------------------------------------------------------------
// Kernel 1: build LUT (one warp per sample point, 33 samples) + unrank table.
// ---------------------------------------------------------------------------
__global__ void build_lut_kernel(const float* __restrict__ w1,
                                 const float* __restrict__ b1,
                                 const float* __restrict__ w2,
                                 const float* __restrict__ b2,
                                 const float* __restrict__ w3,
                                 const float* __restrict__ b3) {
    const int gtid  = blockIdx.x * blockDim.x + threadIdx.x;
    const int gwarp = gtid >> 5;
    const int lane  = threadIdx.x & 31;

    if (gtid < TPAIRS) {
        int t = gtid, ti = 0;
        while (t >= TILE - ti) { t -= TILE - ti; ti++; }
        g_unrank[gtid] = ti | ((ti + t) << 8);
    }
    if (gwarp > NT) return;

    const float x = (float)gwarp * (1.0f / (float)NT);
    float h1 = fmaxf(fmaf(x, w1[lane], b1[lane]), 0.0f);
    float s = b2[lane];
#pragma unroll
    for (int h = 0; h < HDIM; h++) {
        float h1h = __shfl_sync(0xffffffffu, h1, h);
        s = fmaf(h1h, w2[h * HDIM + lane], s);
    }
    float part = fmaxf(s, 0.0f) * w3[lane];
#pragma unroll
    for (int off = 16; off > 0; off >>= 1)
        part += __shfl_xor_sync(0xffffffffu, part, off);

    if (lane == 0) {
        float f = 0.5f / (1.0f + expf(-(part + b3[0])));   // 0.5 folded in
        __half fh = __float2half_rn(f);
        __half* hp = (__half*)g_lut_h2;
        if (gwarp < NT) hp[2 * gwarp]     = fh;   // entry gwarp .x
        if (gwarp > 0)  hp[2 * gwarp - 1] = fh;   // entry gwarp-1 .y
    }
}

// ---------------------------------------------------------------------------
// Register/shuffle LUT lookup: lane l holds entry l; lookup = one SHFL.
// No clamp needed (x in [0,1) by construction). No L1/smem traffic.
// ---------------------------------------------------------------------------
__device__ __forceinline__ float lutf(unsigned lutreg, float x) {
    float u = x * (float)NT;
    int i = (int)u;
    unsigned h = __shfl_sync(0xffffffffu, lutreg, i);
    __half2 hv = *(__half2*)&h;
    float2 v = __half22float2(hv);
    return fmaf(u - (float)i, v.y - v.x, v.x);
}

// ---------------------------------------------------------------------------
// Kernel 2 (R6 structure, LUT moved to shuffle): 512-thread blocks; each
// 256-thread half handles one (b, ti<=tj) tile pair.
//   fwd(r,c)    = fA[r][c] + fB[c][r]
//   mirror(r,c) = fB[r][c] + fA[c][r]
// (fA,fB) staged once as XOR-swizzled float2; one transposed LDS.64 per
// element serves both output tiles.
// ---------------------------------------------------------------------------
__global__ void __launch_bounds__(512)
corrector_kernel(const float* __restrict__ sim,
                 const int* __restrict__ masks,
                 float* __restrict__ out) {
    __shared__ float2 sF[2][TILE * TILE];               // 16 KB (fA,fB) swizzled
    __shared__ __align__(16) float smi[2][TILE];
    __shared__ __align__(16) float smj[2][TILE];

    const int tid  = threadIdx.x;
    const int lane = tid & 31;
    const int half = tid >> 8;
    const int htid = tid & 255;
    const int r    = htid >> 3;
    const int c0   = (htid & 7) * 4;

    // per-lane LUT register (broadcast LDG, cached)
    const unsigned lutreg = ((const unsigned*)g_lut_h2)[lane];

    // pair lookup
    const int p = blockIdx.x * 2 + half;
    const int b = p / TPAIRS;
    const int code = __ldg(&g_unrank[p - b * TPAIRS]);
    const int ti = code & 255;
    const int tj = code >> 8;
    const bool diag = (ti == tj);

    const float* __restrict__ simb = sim + (size_t)b * (NDIM * NDIM);
    float*       __restrict__ outb = out + (size_t)b * (NDIM * NDIM);

    // stage masks (as float 0/1)
    if (htid < TILE)          smi[half][htid]      = (float)masks[b * NDIM + ti * TILE + htid];
    else if (htid < 2 * TILE) smj[half][htid - 32] = (float)masks[b * NDIM + tj * TILE + (htid - 32)];

    // coalesced tile loads
    float4 a4 = *(const float4*)(simb + (size_t)(ti * TILE + r) * NDIM + tj * TILE + c0);
    float4 b4 = diag ? a4
                     : *(const float4*)(simb + (size_t)(tj * TILE + r) * NDIM + ti * TILE + c0);

    // 8 shuffle-LUT lookups (no memory system involvement)
    float fA0 = lutf(lutreg, a4.x), fA1 = lutf(lutreg, a4.y);
    float fA2 = lutf(lutreg, a4.z), fA3 = lutf(lutreg, a4.w);
    float fB0 = lutf(lutreg, b4.x), fB1 = lutf(lutreg, b4.y);
    float fB2 = lutf(lutreg, b4.z), fB3 = lutf(lutreg, b4.w);

    // XOR swizzle: elem(row,col) -> row*32 + (col^row)
    float2* sFh = sF[half];
    const int sbase = r * 32 + (c0 ^ r);
    sFh[sbase ^ 0] = make_float2(fA0, fB0);
    sFh[sbase ^ 1] = make_float2(fA1, fB1);
    sFh[sbase ^ 2] = make_float2(fA2, fB2);
    sFh[sbase ^ 3] = make_float2(fA3, fB3);
    __syncthreads();

    // transposed gather: elem(c0+k, r) at ((lbase)^k) + 32k
    const int lbase = c0 * 32 + (r ^ c0);
    float2 p0 = sFh[(lbase ^ 0)];
    float2 p1 = sFh[(lbase ^ 1) + 32];
    float2 p2 = sFh[(lbase ^ 2) + 64];
    float2 p3 = sFh[(lbase ^ 3) + 96];

    // masks: vectorized column loads, scalar row loads
    const float mi_r = smi[half][r], mj_r = smj[half][r];
    const float4 mj4 = *(const float4*)&smj[half][c0];
    const float4 mi4 = *(const float4*)&smi[half][c0];

    float4 vf;   // fwd tile (ti,tj) row r
    vf.x = (fA0 + p0.y) * (mi_r * mj4.x);
    vf.y = (fA1 + p1.y) * (mi_r * mj4.y);
    vf.z = (fA2 + p2.y) * (mi_r * mj4.z);
    vf.w = (fA3 + p3.y) * (mi_r * mj4.w);
    if (diag) {  // zero the global diagonal (only occurs in diagonal tiles)
        if (r == c0 + 0) vf.x = 0.0f;
        if (r == c0 + 1) vf.y = 0.0f;
        if (r == c0 + 2) vf.z = 0.0f;
        if (r == c0 + 3) vf.w = 0.0f;
    }
    *(float4*)(outb + (size_t)(ti * TILE + r) * NDIM + tj * TILE + c0) = vf;

    if (!diag) {
        float4 vm;  // mirror tile (tj,ti) row r
        vm.x = (fB0 + p0.x) * (mj_r * mi4.x);
        vm.y = (fB1 + p1.x) * (mj_r * mi4.y);
        vm.z = (fB2 + p2.x) * (mj_r * mi4.z);
        vm.w = (fB3 + p3.x) * (mj_r * mi4.w);
        *(float4*)(outb + (size_t)(tj * TILE + r) * NDIM + ti * TILE + c0) = vm;
    }
}

// ---------------------------------------------------------------------------
// Harness entry
// ---------------------------------------------------------------------------
extern "C" void kernel_launch(void* const* d_in, const int* in_sizes, int n_in,
                              void* d_out, int out_size) {
    const float* sim   = (const float*)d_in[0];
    const int*   masks = (const int*)d_in[1];
    const float* w1    = (const float*)d_in[2];
    const float* b1    = (const float*)d_in[3];
    const float* w2    = (const float*)d_in[4];
    const float* b2    = (const float*)d_in[5];
    const float* w3    = (const float*)d_in[6];
    const float* b3    = (const float*)d_in[7];
    float* out = (float*)d_out;

    build_lut_kernel<<<65, 128>>>(w1, b1, w2, b2, w3, b3);  // LUT + unrank table
    corrector_kernel<<<NPAIRS / 2, 512>>>(sim, masks, out);
}